// round 1
// baseline (speedup 1.0000x reference)
#include <cuda_runtime.h>
#include <math.h>

#define B_    2048
#define S_    128
#define D_    1024
#define DFF_  4096
#define NCAND 32
#define NACT  546

#define BM 128
#define BN 128
#define BK 16
#define TM 8
#define TN 8
#define NTHREADS 256

__device__ int g_row[B_];

// Kernel 1: compute first sentinel position per batch, init out = b2.
__global__ void prep_kernel(const int* __restrict__ cand,
                            const float* __restrict__ b2,
                            float* __restrict__ out) {
    int b = blockIdx.x * blockDim.x + threadIdx.x;
    if (b >= B_) return;
    int first = 0;
    // scan from the end so the LAST assignment wins for the FIRST match
    #pragma unroll
    for (int m = NCAND - 1; m >= 0; --m) {
        int c = cand[b * NCAND + m];
        if (c >= NACT) first = m;
    }
    g_row[b] = (S_ - NCAND) + first;
    out[b] = b2[0];
}

__device__ __forceinline__ float gelu_exact(float x) {
    return 0.5f * x * (1.0f + erff(x * 0.70710678118654752f));
}

// Kernel 2: fused gathered-SGEMM + bias + gelu + W2 reduction.
// grid = (DFF_/BN, B_/BM), block = 256.
__global__ __launch_bounds__(NTHREADS, 2)
void fused_mlp_kernel(const float* __restrict__ encode,
                      const float* __restrict__ W1,
                      const float* __restrict__ b1,
                      const float* __restrict__ W2,
                      float* __restrict__ out) {
    __shared__ float As[BK][BM];   // transposed A tile: As[k][m]
    __shared__ float Bs[BK][BN];   // Bs[k][n]

    const int tid = threadIdx.x;
    const int tx = tid & 15;       // n-dim thread coord (0..15)
    const int ty = tid >> 4;       // m-dim thread coord (0..15)
    const int bm = blockIdx.y;
    const int bn = blockIdx.x;

    // ---- A-tile load mapping: 128 rows x 16 k per step = 512 float4; 2/thread
    const int ar0 = tid >> 2;            // row 0..63
    const int akv = (tid & 3) * 4;       // k offset 0,4,8,12
    const float* aptr0;
    const float* aptr1;
    {
        int bb0 = bm * BM + ar0;
        int bb1 = bb0 + 64;
        aptr0 = encode + ((size_t)bb0 * S_ + g_row[bb0]) * D_ + akv;
        aptr1 = encode + ((size_t)bb1 * S_ + g_row[bb1]) * D_ + akv;
    }

    // ---- B-tile load mapping: 16 k rows x 128 n = 512 float4; 2/thread
    const int brow = tid >> 5;           // k row 0..7 (second at +8)
    const int bcol = (tid & 31) * 4;     // n offset
    const float* bptr = W1 + (size_t)brow * DFF_ + bn * BN + bcol;

    float acc[TM][TN];
    #pragma unroll
    for (int i = 0; i < TM; i++)
        #pragma unroll
        for (int j = 0; j < TN; j++) acc[i][j] = 0.f;

    for (int k0 = 0; k0 < D_; k0 += BK) {
        // global loads first (latency overlap with the barrier)
        float4 a0 = *(const float4*)(aptr0 + k0);
        float4 a1 = *(const float4*)(aptr1 + k0);
        float4 w0 = *(const float4*)(bptr + (size_t)k0 * DFF_);
        float4 w1 = *(const float4*)(bptr + (size_t)(k0 + 8) * DFF_);

        __syncthreads();   // previous tile fully consumed

        As[akv + 0][ar0]      = a0.x;
        As[akv + 1][ar0]      = a0.y;
        As[akv + 2][ar0]      = a0.z;
        As[akv + 3][ar0]      = a0.w;
        As[akv + 0][ar0 + 64] = a1.x;
        As[akv + 1][ar0 + 64] = a1.y;
        As[akv + 2][ar0 + 64] = a1.z;
        As[akv + 3][ar0 + 64] = a1.w;
        *(float4*)&Bs[brow][bcol]     = w0;
        *(float4*)&Bs[brow + 8][bcol] = w1;

        __syncthreads();

        #pragma unroll
        for (int kk = 0; kk < BK; kk++) {
            float4 av0 = *(const float4*)&As[kk][ty * TM];
            float4 av1 = *(const float4*)&As[kk][ty * TM + 4];
            float4 bv0 = *(const float4*)&Bs[kk][tx * TN];
            float4 bv1 = *(const float4*)&Bs[kk][tx * TN + 4];
            float a[TM] = {av0.x, av0.y, av0.z, av0.w, av1.x, av1.y, av1.z, av1.w};
            float bf[TN] = {bv0.x, bv0.y, bv0.z, bv0.w, bv1.x, bv1.y, bv1.z, bv1.w};
            #pragma unroll
            for (int i = 0; i < TM; i++)
                #pragma unroll
                for (int j = 0; j < TN; j++)
                    acc[i][j] = fmaf(a[i], bf[j], acc[i][j]);
        }
    }

    // ---- Epilogue: bias + exact gelu + dot with W2, reduce over n
    const int nbase = bn * BN + tx * TN;
    float partial[TM];
    #pragma unroll
    for (int i = 0; i < TM; i++) partial[i] = 0.f;

    #pragma unroll
    for (int j = 0; j < TN; j++) {
        float bb = b1[nbase + j];
        float w2 = W2[nbase + j];
        #pragma unroll
        for (int i = 0; i < TM; i++) {
            float h = gelu_exact(acc[i][j] + bb);
            partial[i] = fmaf(h, w2, partial[i]);
        }
    }

    // reduce across the 16 tx lanes (xor stays inside each 16-lane group)
    #pragma unroll
    for (int i = 0; i < TM; i++) {
        #pragma unroll
        for (int off = 1; off < 16; off <<= 1)
            partial[i] += __shfl_xor_sync(0xffffffffu, partial[i], off);
    }

    if (tx == 0) {
        int mbase = bm * BM + ty * TM;
        #pragma unroll
        for (int i = 0; i < TM; i++)
            atomicAdd(&out[mbase + i], partial[i]);
    }
}

extern "C" void kernel_launch(void* const* d_in, const int* in_sizes, int n_in,
                              void* d_out, int out_size) {
    const int*   cand   = (const int*)d_in[0];
    const float* encode = (const float*)d_in[1];
    const float* W1     = (const float*)d_in[2];
    const float* b1     = (const float*)d_in[3];
    const float* W2     = (const float*)d_in[4];
    const float* b2     = (const float*)d_in[5];
    float* out = (float*)d_out;

    prep_kernel<<<(B_ + 255) / 256, 256>>>(cand, b2, out);

    dim3 grid(DFF_ / BN, B_ / BM);
    fused_mlp_kernel<<<grid, NTHREADS>>>(encode, W1, b1, W2, out);
}

// round 3
// speedup vs baseline: 2.1798x; 2.1798x over previous
#include <cuda_runtime.h>
#include <cuda_bf16.h>
#include <math.h>
#include <stdint.h>

#define B_    2048
#define S_    128
#define D_    1024
#define DFF_  4096
#define NCAND 32
#define NACT  546

#define K3    (3*D_)          // 3072: sections [hi | lo | hi] x [hi | hi | lo]
#define BM    128
#define BN    128
#define BK    64
#define NCH   (K3/BK)         // 48
#define STAGES 3
#define GT    256             // gemm threads (8 warps: 2m x 4n, warp tile 64x32)

#define STAGE_BYTES 32768     // A 16KB + B 16KB
#define SM_TOTAL (STAGES*STAGE_BYTES)

// ---------------- scratch ----------------
__device__ int           g_row[B_];
__device__ __nv_bfloat16 g_A3[(size_t)B_   * K3];   // 12 MB
__device__ __nv_bfloat16 g_B3t[(size_t)DFF_ * K3];  // 24 MB, [n][k]

// ---------------- helpers ----------------
__device__ __forceinline__ uint32_t smem_u32(const void* p) {
    uint32_t a;
    asm("{ .reg .u64 t; cvta.to.shared.u64 t, %1; cvt.u32.u64 %0, t; }" : "=r"(a) : "l"(p));
    return a;
}
__device__ __forceinline__ void cp_async16(uint32_t s, const void* g) {
    asm volatile("cp.async.cg.shared.global [%0], [%1], 16;" :: "r"(s), "l"(g));
}
#define CP_COMMIT() asm volatile("cp.async.commit_group;" ::: "memory")
template <int N>
__device__ __forceinline__ void cp_wait() {
    asm volatile("cp.async.wait_group %0;" :: "n"(N) : "memory");
}
__device__ __forceinline__ void ldsm_x4(uint32_t* r, uint32_t addr) {
    asm volatile("ldmatrix.sync.aligned.m8n8.x4.shared.b16 {%0,%1,%2,%3}, [%4];"
                 : "=r"(r[0]), "=r"(r[1]), "=r"(r[2]), "=r"(r[3]) : "r"(addr));
}
__device__ __forceinline__ void mma16816(float* d, const uint32_t* a, uint32_t b0, uint32_t b1) {
    asm volatile("mma.sync.aligned.m16n8k16.row.col.f32.bf16.bf16.f32 "
                 "{%0,%1,%2,%3}, {%4,%5,%6,%7}, {%8,%9}, {%0,%1,%2,%3};"
                 : "+f"(d[0]), "+f"(d[1]), "+f"(d[2]), "+f"(d[3])
                 : "r"(a[0]), "r"(a[1]), "r"(a[2]), "r"(a[3]), "r"(b0), "r"(b1));
}
__device__ __forceinline__ float gelu_exact(float x) {
    return 0.5f * x * (1.0f + erff(x * 0.70710678118654752f));
}
// swizzled byte offset inside a 128x64-bf16 tile (128B rows): 16B chunk c2, row r
__device__ __forceinline__ uint32_t swz(int r, int c2) {
    return (uint32_t)(r * 128 + ((c2 * 16) ^ ((r & 7) * 16)));
}

// ---------------- kernel 1: sentinel row + out init ----------------
__global__ void prep_kernel(const int* __restrict__ cand,
                            const float* __restrict__ b2,
                            float* __restrict__ out) {
    int b = blockIdx.x * blockDim.x + threadIdx.x;
    if (b >= B_) return;
    int first = 0;
    #pragma unroll
    for (int m = NCAND - 1; m >= 0; --m)
        if (cand[b * NCAND + m] >= NACT) first = m;
    g_row[b] = (S_ - NCAND) + first;
    out[b] = b2[0];
}

// ---------------- kernel 2: gather + split A -> [hi | lo | hi] ----------------
__global__ void convA_kernel(const float* __restrict__ encode) {
    int b = blockIdx.x;
    const float* src = encode + ((size_t)b * S_ + g_row[b]) * D_;
    __nv_bfloat16* dst = g_A3 + (size_t)b * K3;
    for (int k2 = threadIdx.x; k2 < D_ / 2; k2 += blockDim.x) {
        float2 a = *(const float2*)(src + 2 * k2);
        __nv_bfloat16 h0 = __float2bfloat16(a.x);
        __nv_bfloat16 h1 = __float2bfloat16(a.y);
        __nv_bfloat16 l0 = __float2bfloat16(a.x - __bfloat162float(h0));
        __nv_bfloat16 l1 = __float2bfloat16(a.y - __bfloat162float(h1));
        __nv_bfloat162 hv; hv.x = h0; hv.y = h1;
        __nv_bfloat162 lv; lv.x = l0; lv.y = l1;
        *(__nv_bfloat162*)(dst + 2 * k2)            = hv;
        *(__nv_bfloat162*)(dst + D_ + 2 * k2)       = lv;
        *(__nv_bfloat162*)(dst + 2 * D_ + 2 * k2)   = hv;
    }
}

// ---------------- kernel 3: transpose + split W1 -> [hi | hi | lo] ----------------
__global__ void convB_kernel(const float* __restrict__ W1) {
    __shared__ float tile[32][33];
    int n0 = blockIdx.x * 32;
    int k0 = blockIdx.y * 32;
    {
        int nn = threadIdx.x & 31;
        int q  = threadIdx.x >> 5;    // 0..7
        #pragma unroll
        for (int i = 0; i < 4; i++) {
            int kk = q * 4 + i;
            tile[kk][nn] = W1[(size_t)(k0 + kk) * DFF_ + n0 + nn];
        }
    }
    __syncthreads();
    {
        int nn = threadIdx.x >> 3;          // 0..31
        int kq = (threadIdx.x & 7) * 4;     // 0,4,..28
        __nv_bfloat16 hi[4], lo[4];
        #pragma unroll
        for (int i = 0; i < 4; i++) {
            float w = tile[kq + i][nn];
            hi[i] = __float2bfloat16(w);
            lo[i] = __float2bfloat16(w - __bfloat162float(hi[i]));
        }
        __nv_bfloat16* dst = g_B3t + (size_t)(n0 + nn) * K3 + k0 + kq;
        *(uint2*)(dst)           = *(uint2*)hi;
        *(uint2*)(dst + D_)      = *(uint2*)hi;
        *(uint2*)(dst + 2 * D_)  = *(uint2*)lo;
    }
}

// ---------------- kernel 4: bf16 HMMA GEMM + fused epilogue ----------------
__global__ __launch_bounds__(GT)
void gemm_kernel(const float* __restrict__ b1,
                 const float* __restrict__ W2,
                 float* __restrict__ out) {
    extern __shared__ char smem[];
    const uint32_t sb = smem_u32(smem);
    const int tid  = threadIdx.x;
    const int wid  = tid >> 5;
    const int lane = tid & 31;
    const int wm = wid >> 2;     // 0..1
    const int wn = wid & 3;      // 0..3
    const int bn = blockIdx.x;   // 0..31
    const int bm = blockIdx.y;   // 0..15

    const __nv_bfloat16* Ag = g_A3  + (size_t)(bm * BM) * K3;
    const __nv_bfloat16* Bg = g_B3t + (size_t)(bn * BN) * K3;

    // load mapping: 4 chunks of A + 4 of B per thread per stage
    const int lr  = tid >> 3;        // row 0..31 (+32 steps)
    const int lc2 = tid & 7;         // 16B chunk in row

    float acc[4][4][4];
    #pragma unroll
    for (int i = 0; i < 4; i++)
        #pragma unroll
        for (int j = 0; j < 4; j++)
            #pragma unroll
            for (int r = 0; r < 4; r++) acc[i][j][r] = 0.f;

    auto load_stage = [&](int buf, int c) {
        uint32_t sA = sb + buf * STAGE_BYTES;
        uint32_t sB = sA + 16384;
        const __nv_bfloat16* ap = Ag + c * BK + lc2 * 8;
        const __nv_bfloat16* bp = Bg + c * BK + lc2 * 8;
        #pragma unroll
        for (int i = 0; i < 4; i++) {
            int r = lr + i * 32;
            cp_async16(sA + swz(r, lc2), ap + (size_t)r * K3);
            cp_async16(sB + swz(r, lc2), bp + (size_t)r * K3);
        }
    };

    load_stage(0, 0); CP_COMMIT();
    load_stage(1, 1); CP_COMMIT();

    for (int c = 0; c < NCH; c++) {
        cp_wait<1>();
        __syncthreads();
        if (c + 2 < NCH) { load_stage((c + 2) % STAGES, c + 2); CP_COMMIT(); }

        const uint32_t sA = sb + (c % STAGES) * STAGE_BYTES;
        const uint32_t sB = sA + 16384;

        #pragma unroll
        for (int ks = 0; ks < 4; ks++) {
            uint32_t afr[4][4], bfr[2][4];
            const int c2 = ks * 2 + (lane >> 4);
            #pragma unroll
            for (int mt = 0; mt < 4; mt++) {
                int row = wm * 64 + mt * 16 + (lane & 15);
                ldsm_x4(afr[mt], sA + swz(row, c2));
            }
            #pragma unroll
            for (int u = 0; u < 2; u++) {
                int row = wn * 32 + u * 16 + (lane & 15);
                ldsm_x4(bfr[u], sB + swz(row, c2));
            }
            #pragma unroll
            for (int mt = 0; mt < 4; mt++)
                #pragma unroll
                for (int nt = 0; nt < 4; nt++)
                    mma16816(acc[mt][nt], afr[mt],
                             bfr[nt >> 1][nt & 1], bfr[nt >> 1][(nt & 1) + 2]);
        }
    }

    // ---- Epilogue: bias + exact gelu + dot W2, reduce, atomicAdd ----
    const int qn = lane & 3;
    const int qr = lane >> 2;
    float bia[4][2], w2v[4][2];
    #pragma unroll
    for (int nt = 0; nt < 4; nt++) {
        int n = bn * BN + wn * 32 + nt * 8 + qn * 2;
        bia[nt][0] = __ldg(&b1[n]);     bia[nt][1] = __ldg(&b1[n + 1]);
        w2v[nt][0] = __ldg(&W2[n]);     w2v[nt][1] = __ldg(&W2[n + 1]);
    }
    #pragma unroll
    for (int mt = 0; mt < 4; mt++) {
        float p0 = 0.f, p1 = 0.f;
        #pragma unroll
        for (int nt = 0; nt < 4; nt++) {
            const float* d = acc[mt][nt];
            p0 = fmaf(gelu_exact(d[0] + bia[nt][0]), w2v[nt][0], p0);
            p0 = fmaf(gelu_exact(d[1] + bia[nt][1]), w2v[nt][1], p0);
            p1 = fmaf(gelu_exact(d[2] + bia[nt][0]), w2v[nt][0], p1);
            p1 = fmaf(gelu_exact(d[3] + bia[nt][1]), w2v[nt][1], p1);
        }
        p0 += __shfl_xor_sync(0xffffffffu, p0, 1);
        p0 += __shfl_xor_sync(0xffffffffu, p0, 2);
        p1 += __shfl_xor_sync(0xffffffffu, p1, 1);
        p1 += __shfl_xor_sync(0xffffffffu, p1, 2);
        if (qn == 0) {
            int m = bm * BM + wm * 64 + mt * 16 + qr;
            atomicAdd(&out[m], p0);
            atomicAdd(&out[m + 8], p1);
        }
    }
}

// ---------------- launcher ----------------
extern "C" void kernel_launch(void* const* d_in, const int* in_sizes, int n_in,
                              void* d_out, int out_size) {
    const int*   cand   = (const int*)d_in[0];
    const float* encode = (const float*)d_in[1];
    const float* W1     = (const float*)d_in[2];
    const float* b1     = (const float*)d_in[3];
    const float* W2     = (const float*)d_in[4];
    const float* b2     = (const float*)d_in[5];
    float* out = (float*)d_out;

    static int smem_set = 0;
    if (!smem_set) {
        cudaFuncSetAttribute(gemm_kernel, cudaFuncAttributeMaxDynamicSharedMemorySize, SM_TOTAL);
        smem_set = 1;
    }

    prep_kernel<<<(B_ + 255) / 256, 256>>>(cand, b2, out);
    convA_kernel<<<B_, 256>>>(encode);
    {
        dim3 g(DFF_ / 32, D_ / 32);
        convB_kernel<<<g, 256>>>(W1);
    }
    {
        dim3 g(DFF_ / BN, B_ / BM);   // (32, 16)
        gemm_kernel<<<g, GT, SM_TOTAL>>>(b1, W2, out);
    }
}

// round 4
// speedup vs baseline: 2.3664x; 1.0856x over previous
#include <cuda_runtime.h>
#include <cuda_bf16.h>
#include <math.h>
#include <stdint.h>

#define B_    2048
#define S_    128
#define D_    1024
#define DFF_  4096
#define NCAND 32
#define NACT  546

#define K3    (3*D_)          // 3072: sections [hi | lo | hi] x [hi | hi | lo]
#define BM    128
#define BN    128
#define BK    64
#define NCH   (K3/BK)         // 48
#define STAGES 3
#define GT    256             // 8 warps: 2m x 4n, warp tile 64x32

#define STAGE_BYTES 32768     // A 16KB + B 16KB
#define SM_TOTAL (STAGES*STAGE_BYTES)

// ---------------- scratch ----------------
__device__ __nv_bfloat16 g_A3[(size_t)B_   * K3];   // 12 MB
__device__ __nv_bfloat16 g_B3t[(size_t)DFF_ * K3];  // 24 MB, [n][k]

// ---------------- helpers ----------------
__device__ __forceinline__ uint32_t smem_u32(const void* p) {
    uint32_t a;
    asm("{ .reg .u64 t; cvta.to.shared.u64 t, %1; cvt.u32.u64 %0, t; }" : "=r"(a) : "l"(p));
    return a;
}
__device__ __forceinline__ void cp_async16(uint32_t s, const void* g) {
    asm volatile("cp.async.cg.shared.global [%0], [%1], 16;" :: "r"(s), "l"(g));
}
#define CP_COMMIT() asm volatile("cp.async.commit_group;" ::: "memory")
template <int N>
__device__ __forceinline__ void cp_wait() {
    asm volatile("cp.async.wait_group %0;" :: "n"(N) : "memory");
}
__device__ __forceinline__ void ldsm_x4(uint32_t* r, uint32_t addr) {
    asm volatile("ldmatrix.sync.aligned.m8n8.x4.shared.b16 {%0,%1,%2,%3}, [%4];"
                 : "=r"(r[0]), "=r"(r[1]), "=r"(r[2]), "=r"(r[3]) : "r"(addr));
}
__device__ __forceinline__ void mma16816(float* d, const uint32_t* a, uint32_t b0, uint32_t b1) {
    asm volatile("mma.sync.aligned.m16n8k16.row.col.f32.bf16.bf16.f32 "
                 "{%0,%1,%2,%3}, {%4,%5,%6,%7}, {%8,%9}, {%0,%1,%2,%3};"
                 : "+f"(d[0]), "+f"(d[1]), "+f"(d[2]), "+f"(d[3])
                 : "r"(a[0]), "r"(a[1]), "r"(a[2]), "r"(a[3]), "r"(b0), "r"(b1));
}
__device__ __forceinline__ float gelu_exact(float x) {
    return 0.5f * x * (1.0f + erff(x * 0.70710678118654752f));
}
__device__ __forceinline__ uint32_t swz(int r, int c2) {
    return (uint32_t)(r * 128 + ((c2 * 16) ^ ((r & 7) * 16)));
}

// ---------------- kernel 1: fused sentinel + gather + split A ----------------
__global__ void convA_kernel(const int* __restrict__ cand,
                             const float* __restrict__ encode,
                             const float* __restrict__ b2,
                             float* __restrict__ out) {
    const int b = blockIdx.x;
    __shared__ int srow;
    if (threadIdx.x < 32) {
        int c = cand[b * NCAND + threadIdx.x];
        unsigned m = __ballot_sync(0xffffffffu, c >= NACT);
        if (threadIdx.x == 0) {
            srow = (S_ - NCAND) + (__ffs(m) - 1);
            out[b] = b2[0];
        }
    }
    __syncthreads();
    const float* src = encode + ((size_t)b * S_ + srow) * D_;
    __nv_bfloat16* dst = g_A3 + (size_t)b * K3;
    for (int k2 = threadIdx.x; k2 < D_ / 2; k2 += blockDim.x) {
        float2 a = *(const float2*)(src + 2 * k2);
        __nv_bfloat16 h0 = __float2bfloat16(a.x);
        __nv_bfloat16 h1 = __float2bfloat16(a.y);
        __nv_bfloat16 l0 = __float2bfloat16(a.x - __bfloat162float(h0));
        __nv_bfloat16 l1 = __float2bfloat16(a.y - __bfloat162float(h1));
        __nv_bfloat162 hv; hv.x = h0; hv.y = h1;
        __nv_bfloat162 lv; lv.x = l0; lv.y = l1;
        *(__nv_bfloat162*)(dst + 2 * k2)          = hv;
        *(__nv_bfloat162*)(dst + D_ + 2 * k2)     = lv;
        *(__nv_bfloat162*)(dst + 2 * D_ + 2 * k2) = hv;
    }
}

// ---------------- kernel 2: transpose + split W1 -> [hi | hi | lo] ----------------
__global__ void convB_kernel(const float* __restrict__ W1) {
    __shared__ float tile[32][33];
    int n0 = blockIdx.x * 32;
    int k0 = blockIdx.y * 32;
    {
        int nn = threadIdx.x & 31;
        int q  = threadIdx.x >> 5;
        #pragma unroll
        for (int i = 0; i < 4; i++) {
            int kk = q * 4 + i;
            tile[kk][nn] = W1[(size_t)(k0 + kk) * DFF_ + n0 + nn];
        }
    }
    __syncthreads();
    {
        int nn = threadIdx.x >> 3;
        int kq = (threadIdx.x & 7) * 4;
        __nv_bfloat16 hi[4], lo[4];
        #pragma unroll
        for (int i = 0; i < 4; i++) {
            float w = tile[kq + i][nn];
            hi[i] = __float2bfloat16(w);
            lo[i] = __float2bfloat16(w - __bfloat162float(hi[i]));
        }
        __nv_bfloat16* dst = g_B3t + (size_t)(n0 + nn) * K3 + k0 + kq;
        *(uint2*)(dst)          = *(uint2*)hi;
        *(uint2*)(dst + D_)     = *(uint2*)hi;
        *(uint2*)(dst + 2 * D_) = *(uint2*)lo;
    }
}

// ---------------- kernel 3: bf16 HMMA GEMM + fused epilogue ----------------
__global__ __launch_bounds__(GT, 2)
void gemm_kernel(const float* __restrict__ b1,
                 const float* __restrict__ W2,
                 float* __restrict__ out) {
    extern __shared__ char smem[];
    const uint32_t sb = smem_u32(smem);
    const int tid  = threadIdx.x;
    const int wid  = tid >> 5;
    const int lane = tid & 31;
    const int wm = wid >> 2;     // 0..1
    const int wn = wid & 3;      // 0..3
    const int bn = blockIdx.x;   // 0..31
    const int bm = blockIdx.y;   // 0..15

    // ---- cp.async mapping: 8 marching pointers + fixed swizzled smem offsets
    const int lr  = tid >> 3;    // row 0..31
    const int lc2 = tid & 7;     // 16B chunk in row
    const char* aPtr[4];
    const char* bPtr[4];
    uint32_t aSw[4], bSw[4];
    {
        const __nv_bfloat16* Ag = g_A3  + (size_t)(bm * BM) * K3 + lc2 * 8;
        const __nv_bfloat16* Bg = g_B3t + (size_t)(bn * BN) * K3 + lc2 * 8;
        #pragma unroll
        for (int i = 0; i < 4; i++) {
            int r = lr + i * 32;
            aPtr[i] = (const char*)(Ag + (size_t)r * K3);
            bPtr[i] = (const char*)(Bg + (size_t)r * K3);
            aSw[i] = swz(r, lc2);
            bSw[i] = swz(r, lc2) + 16384;
        }
    }

    // ---- ldmatrix address constants (swizzle algebra hoist)
    const int l15 = lane & 15;
    const uint32_t xb  = (uint32_t)(l15 & 7) * 16;
    const uint32_t hlx = ((uint32_t)(lane >> 4) * 16) ^ (xb & 16);
    const uint32_t xh  = xb & 0x60;
    uint32_t ksoff[4];
    #pragma unroll
    for (int ks = 0; ks < 4; ks++) ksoff[ks] = ((uint32_t)ks * 32) ^ xh;
    uint32_t arow[4], brow[2];
    #pragma unroll
    for (int mt = 0; mt < 4; mt++)
        arow[mt] = (uint32_t)(wm * 64 + mt * 16 + l15) * 128 + hlx;
    #pragma unroll
    for (int u = 0; u < 2; u++)
        brow[u] = (uint32_t)(wn * 32 + u * 16 + l15) * 128 + hlx + 16384;

    float acc[4][4][4];
    #pragma unroll
    for (int i = 0; i < 4; i++)
        #pragma unroll
        for (int j = 0; j < 4; j++)
            #pragma unroll
            for (int r = 0; r < 4; r++) acc[i][j][r] = 0.f;

    auto load_stage = [&](uint32_t sbase) {
        #pragma unroll
        for (int i = 0; i < 4; i++) {
            cp_async16(sbase + aSw[i], aPtr[i]);
            cp_async16(sbase + bSw[i], bPtr[i]);
            aPtr[i] += BK * 2;
            bPtr[i] += BK * 2;
        }
    };

    load_stage(sb + 0 * STAGE_BYTES); CP_COMMIT();
    load_stage(sb + 1 * STAGE_BYTES); CP_COMMIT();

    for (int c = 0; c < NCH; c++) {
        cp_wait<1>();
        __syncthreads();
        if (c + 2 < NCH) { load_stage(sb + ((c + 2) % STAGES) * STAGE_BYTES); CP_COMMIT(); }

        const uint32_t sA = sb + (c % STAGES) * STAGE_BYTES;

        #pragma unroll
        for (int ks = 0; ks < 4; ks++) {
            const uint32_t sks = sA + ksoff[ks];
            uint32_t afr[4][4], bfr[2][4];
            #pragma unroll
            for (int mt = 0; mt < 4; mt++) ldsm_x4(afr[mt], sks + arow[mt]);
            #pragma unroll
            for (int u = 0; u < 2; u++)   ldsm_x4(bfr[u],  sks + brow[u]);
            #pragma unroll
            for (int mt = 0; mt < 4; mt++)
                #pragma unroll
                for (int nt = 0; nt < 4; nt++)
                    mma16816(acc[mt][nt], afr[mt],
                             bfr[nt >> 1][nt & 1], bfr[nt >> 1][(nt & 1) + 2]);
        }
    }

    // ---- Epilogue: bias + exact gelu + dot W2, reduce, atomicAdd ----
    const int qn = lane & 3;
    const int qr = lane >> 2;
    float bia[4][2], w2v[4][2];
    #pragma unroll
    for (int nt = 0; nt < 4; nt++) {
        int n = bn * BN + wn * 32 + nt * 8 + qn * 2;
        bia[nt][0] = __ldg(&b1[n]);     bia[nt][1] = __ldg(&b1[n + 1]);
        w2v[nt][0] = __ldg(&W2[n]);     w2v[nt][1] = __ldg(&W2[n + 1]);
    }
    #pragma unroll
    for (int mt = 0; mt < 4; mt++) {
        float p0 = 0.f, p1 = 0.f;
        #pragma unroll
        for (int nt = 0; nt < 4; nt++) {
            const float* d = acc[mt][nt];
            p0 = fmaf(gelu_exact(d[0] + bia[nt][0]), w2v[nt][0], p0);
            p0 = fmaf(gelu_exact(d[1] + bia[nt][1]), w2v[nt][1], p0);
            p1 = fmaf(gelu_exact(d[2] + bia[nt][0]), w2v[nt][0], p1);
            p1 = fmaf(gelu_exact(d[3] + bia[nt][1]), w2v[nt][1], p1);
        }
        p0 += __shfl_xor_sync(0xffffffffu, p0, 1);
        p0 += __shfl_xor_sync(0xffffffffu, p0, 2);
        p1 += __shfl_xor_sync(0xffffffffu, p1, 1);
        p1 += __shfl_xor_sync(0xffffffffu, p1, 2);
        if (qn == 0) {
            int m = bm * BM + wm * 64 + mt * 16 + qr;
            atomicAdd(&out[m], p0);
            atomicAdd(&out[m + 8], p1);
        }
    }
}

// ---------------- launcher ----------------
extern "C" void kernel_launch(void* const* d_in, const int* in_sizes, int n_in,
                              void* d_out, int out_size) {
    const int*   cand   = (const int*)d_in[0];
    const float* encode = (const float*)d_in[1];
    const float* W1     = (const float*)d_in[2];
    const float* b1     = (const float*)d_in[3];
    const float* W2     = (const float*)d_in[4];
    const float* b2     = (const float*)d_in[5];
    float* out = (float*)d_out;

    static int smem_set = 0;
    if (!smem_set) {
        cudaFuncSetAttribute(gemm_kernel, cudaFuncAttributeMaxDynamicSharedMemorySize, SM_TOTAL);
        smem_set = 1;
    }

    convA_kernel<<<B_, 256>>>(cand, encode, b2, out);
    {
        dim3 g(DFF_ / 32, D_ / 32);
        convB_kernel<<<g, 256>>>(W1);
    }
    {
        dim3 g(DFF_ / BN, B_ / BM);   // (32, 16)
        gemm_kernel<<<g, GT, SM_TOTAL>>>(b1, W2, out);
    }
}